// round 16
// baseline (speedup 1.0000x reference)
#include <cuda_runtime.h>

// SiddonConeBP: ray-driven cone-beam backprojection. PASSING FP recipe (frozen):
//  - pix / t / pts: nested FFMA; n2: separate mul/add; L = sqrt.rn
//  - d = ray * (1/L) with 1/L = div.rn(1,L)  [XLA broadcast-divide rewrite]
//  - slab divides: div.rn
//
// R16 perf changes:
//  - lane remap: threadIdx low bits -> v (axial/z). Warp lanes then scatter to
//    32 z-slices (256KB-apart addresses) -> distinct L2 lines/partitions,
//    eliminating LTS partition conflicts of the u-major mapping.
//  - custom float4 zero kernel instead of cudaMemsetAsync.

#define NRAYS   (16 * 128 * 128)
#define NSTEPS  256
#define VOLN    (256 * 256 * 256)

__global__ __launch_bounds__(256) void zero_kernel(float4* __restrict__ p)
{
    int i = blockIdx.x * 256 + threadIdx.x;
    p[i] = make_float4(0.f, 0.f, 0.f, 0.f);
}

__global__ __launch_bounds__(256) void siddon_bp_kernel(
    const float* __restrict__ prj,
    const float* __restrict__ src,
    const float* __restrict__ detc,
    const float* __restrict__ detu,
    const float* __restrict__ detv,
    float* __restrict__ vol)
{
    const float HALF = 128.0f;

    int tid  = blockIdx.x * 256 + threadIdx.x;
    // v-major lane mapping: lane = v (z axis) for LTS partition spread
    int v    = tid & 127;
    int u    = (tid >> 7) & 127;
    int view = tid >> 14;

    const float* s3 = src  + view * 3;
    const float* c3 = detc + view * 3;
    const float* u3 = detu + view * 3;
    const float* v3 = detv + view * 3;

    float sx = s3[0], sy = s3[1], sz = s3[2];

    // uu = (u - 63.5) * 2, vv = (v - 63.5) * 2   (exact in f32)
    float uu = ((float)u - 63.5f) * 2.0f;
    float vv = ((float)v - 63.5f) * 2.0f;

    // pix = (c + vv*vd) + uu*ud  -> nested FFMA (contracted)
    float px = fmaf(uu, u3[0], fmaf(vv, v3[0], c3[0]));
    float py = fmaf(uu, u3[1], fmaf(vv, v3[1], c3[1]));
    float pz = fmaf(uu, u3[2], fmaf(vv, v3[2], c3[2]));

    // ray = pix - s
    float rx = __fsub_rn(px, sx);
    float ry = __fsub_rn(py, sy);
    float rz = __fsub_rn(pz, sz);

    // n2 = ((rx*rx + ry*ry) + rz*rz) -- separate mul/add (reduce emitter)
    float n2 = __fadd_rn(__fadd_rn(__fmul_rn(rx, rx), __fmul_rn(ry, ry)),
                         __fmul_rn(rz, rz));
    float L  = __fsqrt_rn(n2);

    // d = ray * (1/L)  -- XLA broadcast-divide strength reduction
    float rcpL = __fdiv_rn(1.0f, L);
    float dx = __fmul_rn(rx, rcpL);
    float dy = __fmul_rn(ry, rcpL);
    float dz = __fmul_rn(rz, rcpL);

    // dsafe = where(|d| < 1e-9, 1e-9, d)
    float ax = (fabsf(dx) < 1e-9f) ? 1e-9f : dx;
    float ay = (fabsf(dy) < 1e-9f) ? 1e-9f : dy;
    float az = (fabsf(dz) < 1e-9f) ? 1e-9f : dz;

    // slab intersection with [-HALF, HALF]^3 (sub.rn then div.rn)
    float t1x = __fdiv_rn(__fsub_rn(-HALF, sx), ax);
    float t2x = __fdiv_rn(__fsub_rn( HALF, sx), ax);
    float t1y = __fdiv_rn(__fsub_rn(-HALF, sy), ay);
    float t2y = __fdiv_rn(__fsub_rn( HALF, sy), ay);
    float t1z = __fdiv_rn(__fsub_rn(-HALF, sz), az);
    float t2z = __fdiv_rn(__fsub_rn( HALF, sz), az);

    float tmn = fmaxf(fmaxf(fminf(t1x, t2x), fminf(t1y, t2y)), fminf(t1z, t2z));
    float tmx = fminf(fminf(fmaxf(t1x, t2x), fmaxf(t1y, t2y)), fmaxf(t1z, t2z));

    // clip to [0, L]
    tmn = fminf(fmaxf(tmn, 0.0f), L);
    tmx = fminf(fmaxf(tmx, 0.0f), L);

    // ds = max(tmax - tmin, 0) / 256   (division by 2^8 is exact)
    float ds = __fmul_rn(fmaxf(__fsub_rn(tmx, tmn), 0.0f), 0.00390625f);

    // prj index [view, v, u]
    float w = __fmul_rn(prj[(view << 14) + (v << 7) + u], ds);

    if (ds <= 0.0f) return;   // all sample weights are (+/-)0 -> no-op adds

    float tg = 0.5f;          // tgrid = i + 0.5 (exact increments)
    #pragma unroll 4
    for (int i = 0; i < NSTEPS; ++i) {
        // t = fma(tgrid, ds, tmin)   (contracted)
        float t = fmaf(tg, ds, tmn);
        tg = __fadd_rn(tg, 1.0f);
        // pts = fma(t, d, s); q = pts + HALF (separate add; /DX=1 exact)
        float qx = __fadd_rn(fmaf(t, dx, sx), HALF);
        float qy = __fadd_rn(fmaf(t, dy, sy), HALF);
        float qz = __fadd_rn(fmaf(t, dz, sz), HALF);

        int ix = __float2int_rd(qx);   // floor + int cast (F2I.RD)
        int iy = __float2int_rd(qy);
        int iz = __float2int_rd(qz);

        if (((unsigned)ix < 256u) & ((unsigned)iy < 256u) & ((unsigned)iz < 256u)) {
            atomicAdd(vol + ((((iz << 8) + iy) << 8) + ix), w);
        }
    }
}

extern "C" void kernel_launch(void* const* d_in, const int* in_sizes, int n_in,
                              void* d_out, int out_size)
{
    const float* prj  = (const float*)d_in[0];
    const float* src  = (const float*)d_in[1];
    const float* detc = (const float*)d_in[2];
    const float* detu = (const float*)d_in[3];
    const float* detv = (const float*)d_in[4];
    float* vol = (float*)d_out;

    // Zero the 256^3 volume with vectorized stores (float4: 4194304 elems)
    zero_kernel<<<VOLN / 4 / 256, 256>>>((float4*)vol);

    siddon_bp_kernel<<<NRAYS / 256, 256>>>(prj, src, detc, detu, detv, vol);
}

// round 17
// speedup vs baseline: 1.5159x; 1.5159x over previous
#include <cuda_runtime.h>

// SiddonConeBP: ray-driven cone-beam backprojection. PASSING FP recipe (frozen):
//  - pix / t / pts: nested FFMA; n2: separate mul/add; L = sqrt.rn
//  - d = ray * (1/L) with 1/L = div.rn(1,L)  [XLA broadcast-divide rewrite]
//  - slab divides: div.rn
//
// R17: u-major lanes restored (warp atomics coalesce into 1-2 L2 lines —
// measured 233us vs 337us for v-major). zero_kernel kept (7us vs 21us memset).
// Sample loop unrolled 8x.

#define NRAYS   (16 * 128 * 128)
#define NSTEPS  256
#define VOLN    (256 * 256 * 256)

__global__ __launch_bounds__(256) void zero_kernel(float4* __restrict__ p)
{
    int i = blockIdx.x * 256 + threadIdx.x;
    p[i] = make_float4(0.f, 0.f, 0.f, 0.f);
}

__global__ __launch_bounds__(256) void siddon_bp_kernel(
    const float* __restrict__ prj,
    const float* __restrict__ src,
    const float* __restrict__ detc,
    const float* __restrict__ detu,
    const float* __restrict__ detv,
    float* __restrict__ vol)
{
    const float HALF = 128.0f;

    int tid  = blockIdx.x * 256 + threadIdx.x;
    int u    = tid & 127;            // u-major: warp lanes -> adjacent u
    int v    = (tid >> 7) & 127;
    int view = tid >> 14;

    const float* s3 = src  + view * 3;
    const float* c3 = detc + view * 3;
    const float* u3 = detu + view * 3;
    const float* v3 = detv + view * 3;

    float sx = s3[0], sy = s3[1], sz = s3[2];

    // uu = (u - 63.5) * 2, vv = (v - 63.5) * 2   (exact in f32)
    float uu = ((float)u - 63.5f) * 2.0f;
    float vv = ((float)v - 63.5f) * 2.0f;

    // pix = (c + vv*vd) + uu*ud  -> nested FFMA (contracted)
    float px = fmaf(uu, u3[0], fmaf(vv, v3[0], c3[0]));
    float py = fmaf(uu, u3[1], fmaf(vv, v3[1], c3[1]));
    float pz = fmaf(uu, u3[2], fmaf(vv, v3[2], c3[2]));

    // ray = pix - s
    float rx = __fsub_rn(px, sx);
    float ry = __fsub_rn(py, sy);
    float rz = __fsub_rn(pz, sz);

    // n2 = ((rx*rx + ry*ry) + rz*rz) -- separate mul/add (reduce emitter)
    float n2 = __fadd_rn(__fadd_rn(__fmul_rn(rx, rx), __fmul_rn(ry, ry)),
                         __fmul_rn(rz, rz));
    float L  = __fsqrt_rn(n2);

    // d = ray * (1/L)  -- XLA broadcast-divide strength reduction
    float rcpL = __fdiv_rn(1.0f, L);
    float dx = __fmul_rn(rx, rcpL);
    float dy = __fmul_rn(ry, rcpL);
    float dz = __fmul_rn(rz, rcpL);

    // dsafe = where(|d| < 1e-9, 1e-9, d)
    float ax = (fabsf(dx) < 1e-9f) ? 1e-9f : dx;
    float ay = (fabsf(dy) < 1e-9f) ? 1e-9f : dy;
    float az = (fabsf(dz) < 1e-9f) ? 1e-9f : dz;

    // slab intersection with [-HALF, HALF]^3 (sub.rn then div.rn)
    float t1x = __fdiv_rn(__fsub_rn(-HALF, sx), ax);
    float t2x = __fdiv_rn(__fsub_rn( HALF, sx), ax);
    float t1y = __fdiv_rn(__fsub_rn(-HALF, sy), ay);
    float t2y = __fdiv_rn(__fsub_rn( HALF, sy), ay);
    float t1z = __fdiv_rn(__fsub_rn(-HALF, sz), az);
    float t2z = __fdiv_rn(__fsub_rn( HALF, sz), az);

    float tmn = fmaxf(fmaxf(fminf(t1x, t2x), fminf(t1y, t2y)), fminf(t1z, t2z));
    float tmx = fminf(fminf(fmaxf(t1x, t2x), fmaxf(t1y, t2y)), fmaxf(t1z, t2z));

    // clip to [0, L]
    tmn = fminf(fmaxf(tmn, 0.0f), L);
    tmx = fminf(fmaxf(tmx, 0.0f), L);

    // ds = max(tmax - tmin, 0) / 256   (division by 2^8 is exact)
    float ds = __fmul_rn(fmaxf(__fsub_rn(tmx, tmn), 0.0f), 0.00390625f);

    // prj is [view, v, u] contiguous == tid (u-major)
    float w = __fmul_rn(prj[tid], ds);

    if (ds <= 0.0f) return;   // all sample weights are (+/-)0 -> no-op adds

    float tg = 0.5f;          // tgrid = i + 0.5 (exact increments)
    #pragma unroll 8
    for (int i = 0; i < NSTEPS; ++i) {
        // t = fma(tgrid, ds, tmin)   (contracted)
        float t = fmaf(tg, ds, tmn);
        tg = __fadd_rn(tg, 1.0f);
        // pts = fma(t, d, s); q = pts + HALF (separate add; /DX=1 exact)
        float qx = __fadd_rn(fmaf(t, dx, sx), HALF);
        float qy = __fadd_rn(fmaf(t, dy, sy), HALF);
        float qz = __fadd_rn(fmaf(t, dz, sz), HALF);

        int ix = __float2int_rd(qx);   // floor + int cast (F2I.RD)
        int iy = __float2int_rd(qy);
        int iz = __float2int_rd(qz);

        if (((unsigned)ix < 256u) & ((unsigned)iy < 256u) & ((unsigned)iz < 256u)) {
            atomicAdd(vol + ((((iz << 8) + iy) << 8) + ix), w);
        }
    }
}

extern "C" void kernel_launch(void* const* d_in, const int* in_sizes, int n_in,
                              void* d_out, int out_size)
{
    const float* prj  = (const float*)d_in[0];
    const float* src  = (const float*)d_in[1];
    const float* detc = (const float*)d_in[2];
    const float* detu = (const float*)d_in[3];
    const float* detv = (const float*)d_in[4];
    float* vol = (float*)d_out;

    // Zero the 256^3 volume with vectorized stores (float4: 4194304 elems)
    zero_kernel<<<VOLN / 4 / 256, 256>>>((float4*)vol);

    siddon_bp_kernel<<<NRAYS / 256, 256>>>(prj, src, detc, detu, detv, vol);
}